// round 14
// baseline (speedup 1.0000x reference)
#include <cuda_runtime.h>
#include <cuda_bf16.h>
#include <math.h>
#include <stdint.h>

#define SEQ     2048
#define DMODEL  768
#define NLAYER  16
#define DSTATE  64
#define HEADDIM 64
#define DINNER  1536
#define NHEADS  24
#define CONVDIM 1664
#define DINPROJ 3224
#define DINPROJ_PAD 3328
#define CHUNK   256
#define NCHUNK  8
#define VOCAB   32000
#define CONVBLOCKS (SEQ*CONVDIM/256)   // 13312

// ---------------- scratch ----------------
__device__ float g_x  [SEQ*DMODEL];
__device__ float g_zx [SEQ*DINPROJ];     // also reused as out_proj split-K partial buffers
__device__ float g_xBC[SEQ*CONVDIM];
__device__ float g_dt [SEQ*NHEADS];
__device__ float g_acum[NHEADS*SEQ];
__device__ float g_G  [NCHUNK*CHUNK*CHUNK];
__device__ float g_S  [NCHUNK*NHEADS*HEADDIM*DSTATE];
__device__ float g_prev[NCHUNK*NHEADS*HEADDIM*DSTATE];
__device__ float g_y  [SEQ*DINNER];

// activation planes
__device__ __align__(16) __nv_bfloat16 g_ahi[SEQ*DINNER];
__device__ __align__(16) __nv_bfloat16 g_alo[SEQ*DINNER];
// vocab/emb planes
__device__ __align__(16) __nv_bfloat16 g_bhi[VOCAB*DMODEL];
__device__ __align__(16) __nv_bfloat16 g_blo[VOCAB*DMODEL];
// per-layer weight planes (precomputed once per launch)
__device__ __align__(16) __nv_bfloat16 g_wihi[NLAYER*DINPROJ_PAD*DMODEL];
__device__ __align__(16) __nv_bfloat16 g_wilo[NLAYER*DINPROJ_PAD*DMODEL];
__device__ __align__(16) __nv_bfloat16 g_wohi[NLAYER*DMODEL*DINNER];
__device__ __align__(16) __nv_bfloat16 g_wolo[NLAYER*DMODEL*DINNER];

// ======================= PTX helpers =======================
__device__ __forceinline__ uint32_t smem_u32(const void* p){
    uint32_t a; asm("{ .reg .u64 t; cvta.to.shared.u64 t, %1; cvt.u32.u64 %0, t; }" : "=r"(a) : "l"(p));
    return a;
}
#define CP_ASYNC16(dst, src) \
    asm volatile("cp.async.cg.shared.global [%0], [%1], 16;" :: "r"(dst), "l"(src))
#define CP_COMMIT() asm volatile("cp.async.commit_group;" ::: "memory")
#define CP_WAIT(n)  asm volatile("cp.async.wait_group %0;" :: "n"(n) : "memory")

#define LDSM4(r, addr) \
    asm volatile("ldmatrix.sync.aligned.m8n8.x4.shared.b16 {%0,%1,%2,%3}, [%4];" \
        : "=r"((r)[0]), "=r"((r)[1]), "=r"((r)[2]), "=r"((r)[3]) : "r"(addr))

__device__ __forceinline__ void mma_bf16(float* c, const uint32_t* a, const uint32_t* b){
    asm volatile("mma.sync.aligned.m16n8k16.row.col.f32.bf16.bf16.f32 "
        "{%0,%1,%2,%3}, {%4,%5,%6,%7}, {%8,%9}, {%0,%1,%2,%3};"
        : "+f"(c[0]), "+f"(c[1]), "+f"(c[2]), "+f"(c[3])
        : "r"(a[0]), "r"(a[1]), "r"(a[2]), "r"(a[3]), "r"(b[0]), "r"(b[1]));
}

__device__ __forceinline__ void split2(float v0, float v1, uint32_t& hw, uint32_t& lw){
    __nv_bfloat162 h = __floats2bfloat162_rn(v0, v1);
    hw = *reinterpret_cast<uint32_t*>(&h);
    __nv_bfloat162 l = __floats2bfloat162_rn(v0 - __bfloat162float(h.x), v1 - __bfloat162float(h.y));
    lw = *reinterpret_cast<uint32_t*>(&l);
}

// ---------------- vectorized weight split (contiguous) ----------------
__global__ void k_wsplit(const float* __restrict__ src, __nv_bfloat16* __restrict__ hi,
                         __nv_bfloat16* __restrict__ lo, int n, int npad){
    int base = (blockIdx.x*256 + threadIdx.x)*8;
    if (base >= npad) return;
    float v[8];
    if (base + 8 <= n){
        float4 a0 = *(const float4*)(src + base);
        float4 a1 = *(const float4*)(src + base + 4);
        v[0]=a0.x; v[1]=a0.y; v[2]=a0.z; v[3]=a0.w;
        v[4]=a1.x; v[5]=a1.y; v[6]=a1.z; v[7]=a1.w;
    } else {
        #pragma unroll
        for (int i = 0; i < 8; i++) v[i] = (base + i < n) ? src[base+i] : 0.f;
    }
    uint32_t hw[4], lw[4];
    #pragma unroll
    for (int i = 0; i < 4; i++) split2(v[2*i], v[2*i+1], hw[i], lw[i]);
    *(uint4*)(hi + base) = make_uint4(hw[0], hw[1], hw[2], hw[3]);
    *(uint4*)(lo + base) = make_uint4(lw[0], lw[1], lw[2], lw[3]);
}

// ---------------- in_w split with per-layer N padding (3224 -> 3328 rows) ----------------
__global__ void k_wsplit_inw(const float* __restrict__ src,
                             __nv_bfloat16* __restrict__ hi, __nv_bfloat16* __restrict__ lo){
    int base = (blockIdx.x*256 + threadIdx.x)*8;
    if (base >= NLAYER*DINPROJ_PAD*DMODEL) return;
    int layer = base / (DINPROJ_PAD*DMODEL);
    int rem   = base % (DINPROJ_PAD*DMODEL);
    int row   = rem / DMODEL;
    int col   = rem % DMODEL;
    float v[8];
    if (row < DINPROJ){
        const float* s = src + (size_t)layer*DINPROJ*DMODEL + (size_t)row*DMODEL + col;
        float4 a0 = *(const float4*)s;
        float4 a1 = *(const float4*)(s + 4);
        v[0]=a0.x; v[1]=a0.y; v[2]=a0.z; v[3]=a0.w;
        v[4]=a1.x; v[5]=a1.y; v[6]=a1.z; v[7]=a1.w;
    } else {
        #pragma unroll
        for (int i = 0; i < 8; i++) v[i] = 0.f;
    }
    uint32_t hw[4], lw[4];
    #pragma unroll
    for (int i = 0; i < 4; i++) split2(v[2*i], v[2*i+1], hw[i], lw[i]);
    *(uint4*)(hi + base) = make_uint4(hw[0], hw[1], hw[2], hw[3]);
    *(uint4*)(lo + base) = make_uint4(lw[0], lw[1], lw[2], lw[3]);
}

// ======================= 128x128 HMMA bf16x3 GEMM (8 warps, 64x32, 2 CTA/SM) =======================
#define SSTRIDE 40
#define TILE_B (128*SSTRIDE*2)
#define STAGE_B (4*TILE_B)
#define HG_SMEM (2*STAGE_B)

template<int KSPLIT>
__global__ __launch_bounds__(256, 2) void k_hgemm(
    const __nv_bfloat16* __restrict__ Ahi, const __nv_bfloat16* __restrict__ Alo,
    const __nv_bfloat16* __restrict__ Bhi, const __nv_bfloat16* __restrict__ Blo,
    float* __restrict__ C,
    int M, int N, int K)
{
    extern __shared__ __align__(128) char smem[];
    uint32_t sbase = smem_u32(smem);
    int tid = threadIdx.x;
    int bm = blockIdx.y*128, bn = blockIdx.x*128;
    int lane = tid & 31, wid = tid >> 5;
    int warp_m = (wid >> 2)*64, warp_n = (wid & 3)*32;

    int Keff = KSPLIT ? (K >> 1) : K;
    int Koff = KSPLIT ? blockIdx.z * Keff : 0;
    if (KSPLIT) C += (size_t)blockIdx.z * M * N;

    const __nv_bfloat16* gsrc[4] = {Ahi, Alo, Bhi, Blo};

    float acc[4][4][4];
    #pragma unroll
    for (int mi=0;mi<4;mi++)
        #pragma unroll
        for (int ni=0;ni<4;ni++)
            #pragma unroll
            for (int q=0;q<4;q++) acc[mi][ni][q]=0.f;

    const int NCK = Keff/32;

    int sub = lane >> 3, r = lane & 7;
    uint32_t aoff = (uint32_t)((warp_m + (sub&1)*8 + r)*(SSTRIDE*2) + (sub>>1)*16);
    uint32_t boff = (uint32_t)((warp_n + (sub>>1)*8 + r)*(SSTRIDE*2) + (sub&1)*16);

    auto load_stage = [&](int kc, int buf){
        if (kc < NCK){
            uint32_t sb = sbase + buf*STAGE_B;
            #pragma unroll
            for (int i = 0; i < 8; i++){
                int tile = i >> 1;
                int within = (i&1)*256 + tid;
                int row = within >> 2, ch = within & 3;
                int grow = ((tile < 2) ? bm : bn) + row;
                const __nv_bfloat16* src = gsrc[tile] + (size_t)grow*K + Koff + kc*32 + ch*8;
                uint32_t dst = sb + tile*TILE_B + row*(SSTRIDE*2) + ch*16;
                CP_ASYNC16(dst, src);
            }
        }
        CP_COMMIT();
    };

    load_stage(0, 0);
    load_stage(1, 1);

    for (int kc = 0; kc < NCK; kc++){
        int buf = kc & 1;
        CP_WAIT(1);
        __syncthreads();

        uint32_t sb = sbase + buf*STAGE_B;
        #pragma unroll
        for (int kk = 0; kk < 32; kk += 16){
            uint32_t bh[2][4], bl[2][4];
            #pragma unroll
            for (int nb = 0; nb < 2; nb++){
                uint32_t bd = sb + 2*TILE_B + boff + (uint32_t)(nb*16*(SSTRIDE*2) + kk*2);
                LDSM4(bh[nb], bd);
                LDSM4(bl[nb], bd + TILE_B);
            }
            #pragma unroll
            for (int mp = 0; mp < 4; mp += 2){
                uint32_t ah[2][4], al[2][4];
                #pragma unroll
                for (int q = 0; q < 2; q++){
                    uint32_t ad = sb + aoff + (uint32_t)((mp+q)*16*(SSTRIDE*2) + kk*2);
                    LDSM4(ah[q], ad);
                    LDSM4(al[q], ad + TILE_B);
                }
                #pragma unroll
                for (int q = 0; q < 2; q++)
                    #pragma unroll
                    for (int nb = 0; nb < 2; nb++)
                        #pragma unroll
                        for (int half = 0; half < 2; half++)
                            mma_bf16(acc[mp+q][nb*2+half], ah[q], &bh[nb][half*2]);
                #pragma unroll
                for (int q = 0; q < 2; q++)
                    #pragma unroll
                    for (int nb = 0; nb < 2; nb++)
                        #pragma unroll
                        for (int half = 0; half < 2; half++)
                            mma_bf16(acc[mp+q][nb*2+half], ah[q], &bl[nb][half*2]);
                #pragma unroll
                for (int q = 0; q < 2; q++)
                    #pragma unroll
                    for (int nb = 0; nb < 2; nb++)
                        #pragma unroll
                        for (int half = 0; half < 2; half++)
                            mma_bf16(acc[mp+q][nb*2+half], al[q], &bh[nb][half*2]);
            }
        }
        __syncthreads();
        load_stage(kc+2, buf);
    }

    int g = lane >> 2, t = lane & 3;
    #pragma unroll
    for (int mi = 0; mi < 4; mi++){
        int r0 = bm + warp_m + mi*16 + g;
        #pragma unroll
        for (int ni = 0; ni < 4; ni++){
            int col = bn + warp_n + ni*8 + 2*t;
            if (col < N){
                *(float2*)(C + (size_t)r0*N + col)     = make_float2(acc[mi][ni][0], acc[mi][ni][1]);
                *(float2*)(C + (size_t)(r0+8)*N + col) = make_float2(acc[mi][ni][2], acc[mi][ni][3]);
            }
        }
    }
}

// ---------------- fused embedding gather + rmsnorm + split ----------------
__global__ void k_embednorm(const int* __restrict__ ids, const float* __restrict__ emb,
                            const float* __restrict__ w,
                            __nv_bfloat16* __restrict__ hi, __nv_bfloat16* __restrict__ lo){
    int t = blockIdx.x, tid = threadIdx.x;
    int row = ids[t];
    __shared__ float buf[DMODEL];
    __shared__ float red[256];
    float ss = 0.f;
    for (int d = tid; d < DMODEL; d += 256){
        float v = emb[(size_t)row*DMODEL + d];
        g_x[(size_t)t*DMODEL + d] = v;
        buf[d] = v;
        ss += v*v;
    }
    red[tid] = ss; __syncthreads();
    for (int o = 128; o > 0; o >>= 1){ if (tid < o) red[tid] += red[tid+o]; __syncthreads(); }
    float sc = rsqrtf(red[0]/(float)DMODEL + 1e-6f);
    for (int d = tid*2; d < DMODEL; d += 512){
        float v0 = buf[d]*sc*w[d];
        float v1 = buf[d+1]*sc*w[d+1];
        uint32_t hw, lw; split2(v0, v1, hw, lw);
        *(uint32_t*)(hi + (size_t)t*DMODEL + d) = hw;
        *(uint32_t*)(lo + (size_t)t*DMODEL + d) = lw;
    }
}

// ---------------- fused residual add + rmsnorm + split ----------------
__global__ void k_addnorm(const float* __restrict__ c0, const float* __restrict__ c1,
                          const float* __restrict__ w,
                          __nv_bfloat16* __restrict__ hi, __nv_bfloat16* __restrict__ lo){
    int t = blockIdx.x, tid = threadIdx.x;
    __shared__ float buf[DMODEL];
    __shared__ float red[256];
    float ss = 0.f;
    for (int d = tid; d < DMODEL; d += 256){
        size_t idx = (size_t)t*DMODEL + d;
        float v = g_x[idx] + c0[idx] + c1[idx];
        g_x[idx] = v;
        buf[d] = v;
        ss += v*v;
    }
    red[tid] = ss; __syncthreads();
    for (int o = 128; o > 0; o >>= 1){ if (tid < o) red[tid] += red[tid+o]; __syncthreads(); }
    float sc = rsqrtf(red[0]/(float)DMODEL + 1e-6f);
    for (int d = tid*2; d < DMODEL; d += 512){
        float v0 = buf[d]*sc*w[d];
        float v1 = buf[d+1]*sc*w[d+1];
        uint32_t hw, lw; split2(v0, v1, hw, lw);
        *(uint32_t*)(hi + (size_t)t*DMODEL + d) = hw;
        *(uint32_t*)(lo + (size_t)t*DMODEL + d) = lw;
    }
}

// ---------------- gated rmsnorm -> bf16 hi/lo ----------------
__global__ void k_gatenorm_split(const float* __restrict__ gw,
                                 __nv_bfloat16* __restrict__ hi, __nv_bfloat16* __restrict__ lo){
    int t = blockIdx.x, tid = threadIdx.x;
    __shared__ float v[DINNER];
    __shared__ float red[256];
    float ss = 0.f;
    for (int d = tid; d < DINNER; d += 256){
        float z = g_zx[(size_t)t*DINPROJ + d];
        float sil = z / (1.f + __expf(-z));
        float val = g_y[(size_t)t*DINNER + d] * sil;
        v[d] = val; ss += val*val;
    }
    red[tid] = ss; __syncthreads();
    for (int o = 128; o > 0; o >>= 1){ if (tid < o) red[tid] += red[tid+o]; __syncthreads(); }
    float sc = rsqrtf(red[0]/(float)DINNER + 1e-5f);
    for (int d = tid*2; d < DINNER; d += 512){
        float v0 = v[d]*sc*gw[d];
        float v1 = v[d+1]*sc*gw[d+1];
        uint32_t hw, lw; split2(v0, v1, hw, lw);
        *(uint32_t*)(hi + (size_t)t*DINNER + d) = hw;
        *(uint32_t*)(lo + (size_t)t*DINNER + d) = lw;
    }
}

// ---------------- fused conv+silu | dt+cumsum ----------------
__global__ void k_convcum(const float* __restrict__ cw, const float* __restrict__ cb,
                          const float* __restrict__ A_log, const float* __restrict__ dtb){
    int b = blockIdx.x, tid = threadIdx.x;
    if (b < CONVBLOCKS){
        int idx = b*256 + tid;
        int t = idx / CONVDIM, ch = idx % CONVDIM;
        float acc = cb[ch];
        #pragma unroll
        for (int k = 0; k < 4; k++){
            int tt = t - 3 + k;
            if (tt >= 0) acc += cw[ch*4 + k] * g_zx[(size_t)tt*DINPROJ + DINNER + ch];
        }
        g_xBC[idx] = acc / (1.f + __expf(-acc));
    } else {
        int bb = b - CONVBLOCKS;
        int h = bb % NHEADS, c = bb / NHEADS;
        float A = -__expf(A_log[h]);
        __shared__ float s[CHUNK];
        int tg = c*CHUNK + tid;
        float x = g_zx[(size_t)tg*DINPROJ + DINNER + CONVDIM + h] + dtb[h];
        float dtv = (x > 20.f) ? x : log1pf(__expf(x));
        g_dt[(size_t)tg*NHEADS + h] = dtv;
        float v = dtv * A;
        s[tid] = v; __syncthreads();
        for (int o = 1; o < CHUNK; o <<= 1){
            float add = (tid >= o) ? s[tid - o] : 0.f;
            __syncthreads();
            s[tid] += add;
            __syncthreads();
        }
        g_acum[(size_t)h*SEQ + c*CHUNK + tid] = s[tid];
    }
}

// ---------------- fused G | states ----------------
__global__ __launch_bounds__(256) void k_Gstates(){
    __shared__ __align__(16) float sh[4096];
    int b = blockIdx.x, tid = threadIdx.x;
    if (b < 128){
        int c = b >> 4, rest = b & 15;
        int s0 = (rest >> 2)*64, l0 = (rest & 3)*64;
        float (*Bs)[64] = (float(*)[64])sh;
        float (*Cs)[64] = (float(*)[64])(sh + 1024);
        int ty = tid/16, tx = tid%16;
        int lr = tid/4, lk = (tid%4)*4;
        float acc[4][4];
        #pragma unroll
        for (int i=0;i<4;i++)
            #pragma unroll
            for (int j=0;j<4;j++) acc[i][j]=0.f;
        const float* base = g_xBC + (size_t)(c*CHUNK)*CONVDIM;
        for (int k0 = 0; k0 < DSTATE; k0 += 16){
            __syncthreads();
            float4 b4 = *(const float4*)(base + (size_t)(s0+lr)*CONVDIM + DINNER + k0 + lk);
            float4 c4 = *(const float4*)(base + (size_t)(l0+lr)*CONVDIM + DINNER + DSTATE + k0 + lk);
            Bs[lk+0][lr]=b4.x; Bs[lk+1][lr]=b4.y; Bs[lk+2][lr]=b4.z; Bs[lk+3][lr]=b4.w;
            Cs[lk+0][lr]=c4.x; Cs[lk+1][lr]=c4.y; Cs[lk+2][lr]=c4.z; Cs[lk+3][lr]=c4.w;
            __syncthreads();
            #pragma unroll
            for (int k = 0; k < 16; k++){
                float a[4], bb[4];
                #pragma unroll
                for (int i=0;i<4;i++) a[i] = Bs[k][ty*4+i];
                #pragma unroll
                for (int j=0;j<4;j++) bb[j] = Cs[k][tx*4+j];
                #pragma unroll
                for (int i=0;i<4;i++)
                    #pragma unroll
                    for (int j=0;j<4;j++) acc[i][j] += a[i]*bb[j];
            }
        }
        #pragma unroll
        for (int i=0;i<4;i++){
            int sidx = s0 + ty*4 + i;
            #pragma unroll
            for (int j=0;j<4;j++)
                g_G[(size_t)c*CHUNK*CHUNK + (size_t)sidx*CHUNK + (l0 + tx*4 + j)] = acc[i][j];
        }
    } else {
        int bb = b - 128;
        int c = bb & 7, h = bb >> 3;
        float* sB = sh;
        float* sX = sh + 2048;
        int pi = tid >> 2, ng = tid & 3;
        float acc[16];
        #pragma unroll
        for (int i=0;i<16;i++) acc[i]=0.f;
        const float* acum = g_acum + (size_t)h*SEQ + c*CHUNK;
        float alast = acum[CHUNK-1];
        for (int s0 = 0; s0 < CHUNK; s0 += 32){
            __syncthreads();
            #pragma unroll
            for (int i = 0; i < 8; i++){
                int idx = i*256 + tid; int ssi = idx>>6, n = idx&63;
                int t = c*CHUNK + s0 + ssi;
                sB[idx] = g_xBC[(size_t)t*CONVDIM + DINNER + n];
                float d  = g_dt[(size_t)t*NHEADS + h];
                float dec = __expf(alast - acum[s0+ssi]);
                sX[idx] = g_xBC[(size_t)t*CONVDIM + h*HEADDIM + n] * d * dec;
            }
            __syncthreads();
            for (int ssi = 0; ssi < 32; ssi++){
                float xv = sX[ssi*64 + pi];
                const float4* b4p = (const float4*)(sB + ssi*64 + ng*16);
                #pragma unroll
                for (int j = 0; j < 4; j++){
                    float4 bv = b4p[j];
                    acc[j*4+0] += xv*bv.x; acc[j*4+1] += xv*bv.y;
                    acc[j*4+2] += xv*bv.z; acc[j*4+3] += xv*bv.w;
                }
            }
        }
        float* out = g_S + (size_t)(c*NHEADS + h)*HEADDIM*DSTATE + pi*DSTATE + ng*16;
        #pragma unroll
        for (int j = 0; j < 4; j++)
            *(float4*)(out + j*4) = make_float4(acc[j*4+0], acc[j*4+1], acc[j*4+2], acc[j*4+3]);
    }
}

// ---------------- cross-chunk recurrence (parallel over elements) ----------------
__global__ void k_recur(){
    int idx4 = blockIdx.x*256 + threadIdx.x;      // float4 index, 0..24575
    int h = idx4 >> 10;
    int e = (idx4 & 1023) * 4;
    float4 r = make_float4(0.f, 0.f, 0.f, 0.f);
    #pragma unroll
    for (int c = 0; c < NCHUNK; c++){
        float dec = __expf(g_acum[(size_t)h*SEQ + c*CHUNK + CHUNK-1]);
        size_t base = (size_t)(c*NHEADS + h)*HEADDIM*DSTATE + e;
        *(float4*)(g_prev + base) = r;
        float4 s = *(const float4*)(g_S + base);
        r.x = r.x*dec + s.x; r.y = r.y*dec + s.y;
        r.z = r.z*dec + s.z; r.w = r.w*dec + s.w;
    }
}

// ---------------- fused Y_off + Y_diag, split over p-halves ----------------
// grid (NCHUNK, NHEADS, 2); z selects p range [z*32, z*32+32)
__global__ __launch_bounds__(256) void k_yoffy(const float* __restrict__ Dskip){
    int c = blockIdx.x, h = blockIdx.y;
    int p0 = blockIdx.z * 32;
    __shared__ __align__(16) float sbuf[2048];   // prev[32 x 64] then reused as sX[32 x 32]
    __shared__ float sac[CHUNK];
    int tid = threadIdx.x, l = tid;
    sac[tid] = g_acum[(size_t)h*SEQ + c*CHUNK + tid];
    size_t base = (size_t)(c*NHEADS + h)*HEADDIM*DSTATE + (size_t)p0*DSTATE;
    #pragma unroll
    for (int i = 0; i < 8; i++) sbuf[i*256 + tid] = g_prev[base + i*256 + tid];
    __syncthreads();
    float aL = sac[l];
    float eL = __expf(aL);
    float acc[32];
    {   // Y_off for p in [p0, p0+32)
        const float4* Crow = (const float4*)(g_xBC + (size_t)(c*CHUNK + l)*CONVDIM + DINNER + DSTATE);
        float4 cr[16];
        #pragma unroll
        for (int i = 0; i < 16; i++) cr[i] = Crow[i];
        const float4* ps4 = (const float4*)sbuf;
        for (int p = 0; p < 32; p++){
            float s = 0.f;
            #pragma unroll
            for (int i = 0; i < 16; i++){
                float4 bv = ps4[p*16 + i];
                s += cr[i].x*bv.x + cr[i].y*bv.y + cr[i].z*bv.z + cr[i].w*bv.w;
            }
            acc[p] = eL*s;
        }
    }
    const float* Gt = g_G + (size_t)c*CHUNK*CHUNK;
    float* sX = sbuf;                            // 32 s x 32 p
    for (int s0 = 0; s0 < CHUNK; s0 += 32){
        __syncthreads();
        #pragma unroll
        for (int i = 0; i < 4; i++){
            int idx = i*256 + tid; int ssi = idx>>5, pp = idx&31;
            int t = c*CHUNK + s0 + ssi;
            sX[idx] = g_xBC[(size_t)t*CONVDIM + h*HEADDIM + p0 + pp] * g_dt[(size_t)t*NHEADS + h];
        }
        __syncthreads();
        int smax = l - s0 + 1; if (smax > 32) smax = 32;
        for (int ssi = 0; ssi < smax; ssi++){
            int s = s0 + ssi;
            float g = Gt[(size_t)s*CHUNK + l] * __expf(aL - sac[s]);
            const float4* x4 = (const float4*)(sX + ssi*32);
            #pragma unroll
            for (int p = 0; p < 8; p++){
                float4 xv = x4[p];
                acc[p*4+0] += g*xv.x; acc[p*4+1] += g*xv.y;
                acc[p*4+2] += g*xv.z; acc[p*4+3] += g*xv.w;
            }
        }
    }
    float dsk = Dskip[h];
    int t = c*CHUNK + l;
    float* yo = g_y + (size_t)t*DINNER + h*HEADDIM + p0;
    const float* xr = g_xBC + (size_t)t*CONVDIM + h*HEADDIM + p0;
    #pragma unroll
    for (int p = 0; p < 32; p++) yo[p] = acc[p] + dsk*xr[p];
}

// ---------------- host orchestration ----------------
extern "C" void kernel_launch(void* const* d_in, const int* in_sizes, int n_in,
                              void* d_out, int out_size){
    const int*   ids     = (const int*)  d_in[0];
    const float* emb     = (const float*)d_in[1];
    const float* ln_w    = (const float*)d_in[2];
    const float* in_w    = (const float*)d_in[3];
    const float* conv_w  = (const float*)d_in[4];
    const float* conv_b  = (const float*)d_in[5];
    const float* dt_b    = (const float*)d_in[6];
    const float* A_log   = (const float*)d_in[7];
    const float* D_skip  = (const float*)d_in[8];
    const float* gnorm_w = (const float*)d_in[9];
    const float* out_w   = (const float*)d_in[10];
    const float* norm_f  = (const float*)d_in[11];
    float* out = (float*)d_out;

    float *px, *pzx;
    __nv_bfloat16 *pahi, *palo, *pbhi, *pblo, *pwihi, *pwilo, *pwohi, *pwolo;
    cudaGetSymbolAddress((void**)&px,  g_x);
    cudaGetSymbolAddress((void**)&pzx, g_zx);
    cudaGetSymbolAddress((void**)&pahi, g_ahi);
    cudaGetSymbolAddress((void**)&palo, g_alo);
    cudaGetSymbolAddress((void**)&pbhi, g_bhi);
    cudaGetSymbolAddress((void**)&pblo, g_blo);
    cudaGetSymbolAddress((void**)&pwihi, g_wihi);
    cudaGetSymbolAddress((void**)&pwilo, g_wilo);
    cudaGetSymbolAddress((void**)&pwohi, g_wohi);
    cudaGetSymbolAddress((void**)&pwolo, g_wolo);

    cudaFuncSetAttribute(k_hgemm<0>, cudaFuncAttributeMaxDynamicSharedMemorySize, HG_SMEM);
    cudaFuncSetAttribute(k_hgemm<1>, cudaFuncAttributeMaxDynamicSharedMemorySize, HG_SMEM);

    // ---- prologue: all weight splits (constant data) ----
    k_wsplit_inw<<<(NLAYER*DINPROJ_PAD*DMODEL/8 + 255)/256, 256>>>(in_w, pwihi, pwilo);
    k_wsplit<<<(NLAYER*DMODEL*DINNER/8 + 255)/256, 256>>>(out_w, pwohi, pwolo,
                                                          NLAYER*DMODEL*DINNER, NLAYER*DMODEL*DINNER);
    k_wsplit<<<(VOCAB*DMODEL/8 + 255)/256, 256>>>(emb, pbhi, pblo, VOCAB*DMODEL, VOCAB*DMODEL);

    k_embednorm<<<SEQ, 256>>>(ids, emb, ln_w, pahi, palo);
    for (int i = 0; i < NLAYER; i++){
        k_hgemm<0><<<dim3(DINPROJ_PAD/128, SEQ/128), 256, HG_SMEM>>>(
            pahi, palo,
            pwihi + (size_t)i*DINPROJ_PAD*DMODEL, pwilo + (size_t)i*DINPROJ_PAD*DMODEL,
            pzx, SEQ, DINPROJ, DMODEL);

        k_convcum<<<CONVBLOCKS + NHEADS*NCHUNK, 256>>>(conv_w + (size_t)i*CONVDIM*4,
                                                       conv_b + i*CONVDIM,
                                                       A_log + i*NHEADS, dt_b + i*NHEADS);
        k_Gstates<<<128 + NCHUNK*NHEADS, 256>>>();
        k_recur<<<NHEADS*HEADDIM*DSTATE/4/256, 256>>>();
        k_yoffy<<<dim3(NCHUNK, NHEADS, 2), 256>>>(D_skip + i*NHEADS);
        k_gatenorm_split<<<SEQ, 256>>>(gnorm_w + (size_t)i*DINNER, pahi, palo);

        k_hgemm<1><<<dim3(DMODEL/128, SEQ/128, 2), 256, HG_SMEM>>>(
            pahi, palo,
            pwohi + (size_t)i*DMODEL*DINNER, pwolo + (size_t)i*DMODEL*DINNER,
            pzx, SEQ, DMODEL, DINNER);
        const float* wnext = (i + 1 < NLAYER) ? (ln_w + (size_t)(i+1)*DMODEL) : norm_f;
        k_addnorm<<<SEQ, 256>>>(pzx, pzx + SEQ*DMODEL, wnext, pahi, palo);
    }
    k_hgemm<0><<<dim3(VOCAB/128, SEQ/128), 256, HG_SMEM>>>(
        pahi, palo, pbhi, pblo, out, SEQ, VOCAB, DMODEL);
}

// round 15
// speedup vs baseline: 1.0031x; 1.0031x over previous
#include <cuda_runtime.h>
#include <cuda_bf16.h>
#include <math.h>
#include <stdint.h>

#define SEQ     2048
#define DMODEL  768
#define NLAYER  16
#define DSTATE  64
#define HEADDIM 64
#define DINNER  1536
#define NHEADS  24
#define CONVDIM 1664
#define DINPROJ 3224
#define DINPROJ_PAD 3328
#define CHUNK   256
#define NCHUNK  8
#define VOCAB   32000
#define CONVBLOCKS (SEQ*CONVDIM/256)   // 13312

// ---------------- scratch ----------------
__device__ float g_x  [SEQ*DMODEL];
__device__ float g_zx [SEQ*DINPROJ];     // also reused as out_proj split-K partial buffers
__device__ float g_xBC[SEQ*CONVDIM];
__device__ float g_dt [SEQ*NHEADS];
__device__ float g_acum[NHEADS*SEQ];
__device__ float g_G  [NCHUNK*CHUNK*CHUNK];
__device__ float g_S  [NCHUNK*NHEADS*HEADDIM*DSTATE];
__device__ float g_y  [SEQ*DINNER];

// activation planes
__device__ __align__(16) __nv_bfloat16 g_ahi[SEQ*DINNER];
__device__ __align__(16) __nv_bfloat16 g_alo[SEQ*DINNER];
// vocab/emb planes
__device__ __align__(16) __nv_bfloat16 g_bhi[VOCAB*DMODEL];
__device__ __align__(16) __nv_bfloat16 g_blo[VOCAB*DMODEL];
// per-layer weight planes (precomputed once per launch)
__device__ __align__(16) __nv_bfloat16 g_wihi[NLAYER*DINPROJ_PAD*DMODEL];
__device__ __align__(16) __nv_bfloat16 g_wilo[NLAYER*DINPROJ_PAD*DMODEL];
__device__ __align__(16) __nv_bfloat16 g_wohi[NLAYER*DMODEL*DINNER];
__device__ __align__(16) __nv_bfloat16 g_wolo[NLAYER*DMODEL*DINNER];

// ======================= PTX helpers =======================
__device__ __forceinline__ uint32_t smem_u32(const void* p){
    uint32_t a; asm("{ .reg .u64 t; cvta.to.shared.u64 t, %1; cvt.u32.u64 %0, t; }" : "=r"(a) : "l"(p));
    return a;
}
#define CP_ASYNC16(dst, src) \
    asm volatile("cp.async.cg.shared.global [%0], [%1], 16;" :: "r"(dst), "l"(src))
#define CP_COMMIT() asm volatile("cp.async.commit_group;" ::: "memory")
#define CP_WAIT(n)  asm volatile("cp.async.wait_group %0;" :: "n"(n) : "memory")

#define LDSM4(r, addr) \
    asm volatile("ldmatrix.sync.aligned.m8n8.x4.shared.b16 {%0,%1,%2,%3}, [%4];" \
        : "=r"((r)[0]), "=r"((r)[1]), "=r"((r)[2]), "=r"((r)[3]) : "r"(addr))

__device__ __forceinline__ void mma_bf16(float* c, const uint32_t* a, const uint32_t* b){
    asm volatile("mma.sync.aligned.m16n8k16.row.col.f32.bf16.bf16.f32 "
        "{%0,%1,%2,%3}, {%4,%5,%6,%7}, {%8,%9}, {%0,%1,%2,%3};"
        : "+f"(c[0]), "+f"(c[1]), "+f"(c[2]), "+f"(c[3])
        : "r"(a[0]), "r"(a[1]), "r"(a[2]), "r"(a[3]), "r"(b[0]), "r"(b[1]));
}

__device__ __forceinline__ void split2(float v0, float v1, uint32_t& hw, uint32_t& lw){
    __nv_bfloat162 h = __floats2bfloat162_rn(v0, v1);
    hw = *reinterpret_cast<uint32_t*>(&h);
    __nv_bfloat162 l = __floats2bfloat162_rn(v0 - __bfloat162float(h.x), v1 - __bfloat162float(h.y));
    lw = *reinterpret_cast<uint32_t*>(&l);
}

// ---------------- vectorized weight split (contiguous) ----------------
__global__ void k_wsplit(const float* __restrict__ src, __nv_bfloat16* __restrict__ hi,
                         __nv_bfloat16* __restrict__ lo, int n, int npad){
    int base = (blockIdx.x*256 + threadIdx.x)*8;
    if (base >= npad) return;
    float v[8];
    if (base + 8 <= n){
        float4 a0 = *(const float4*)(src + base);
        float4 a1 = *(const float4*)(src + base + 4);
        v[0]=a0.x; v[1]=a0.y; v[2]=a0.z; v[3]=a0.w;
        v[4]=a1.x; v[5]=a1.y; v[6]=a1.z; v[7]=a1.w;
    } else {
        #pragma unroll
        for (int i = 0; i < 8; i++) v[i] = (base + i < n) ? src[base+i] : 0.f;
    }
    uint32_t hw[4], lw[4];
    #pragma unroll
    for (int i = 0; i < 4; i++) split2(v[2*i], v[2*i+1], hw[i], lw[i]);
    *(uint4*)(hi + base) = make_uint4(hw[0], hw[1], hw[2], hw[3]);
    *(uint4*)(lo + base) = make_uint4(lw[0], lw[1], lw[2], lw[3]);
}

// ---------------- in_w split with per-layer N padding (3224 -> 3328 rows) ----------------
__global__ void k_wsplit_inw(const float* __restrict__ src,
                             __nv_bfloat16* __restrict__ hi, __nv_bfloat16* __restrict__ lo){
    int base = (blockIdx.x*256 + threadIdx.x)*8;
    if (base >= NLAYER*DINPROJ_PAD*DMODEL) return;
    int layer = base / (DINPROJ_PAD*DMODEL);
    int rem   = base % (DINPROJ_PAD*DMODEL);
    int row   = rem / DMODEL;
    int col   = rem % DMODEL;
    float v[8];
    if (row < DINPROJ){
        const float* s = src + (size_t)layer*DINPROJ*DMODEL + (size_t)row*DMODEL + col;
        float4 a0 = *(const float4*)s;
        float4 a1 = *(const float4*)(s + 4);
        v[0]=a0.x; v[1]=a0.y; v[2]=a0.z; v[3]=a0.w;
        v[4]=a1.x; v[5]=a1.y; v[6]=a1.z; v[7]=a1.w;
    } else {
        #pragma unroll
        for (int i = 0; i < 8; i++) v[i] = 0.f;
    }
    uint32_t hw[4], lw[4];
    #pragma unroll
    for (int i = 0; i < 4; i++) split2(v[2*i], v[2*i+1], hw[i], lw[i]);
    *(uint4*)(hi + base) = make_uint4(hw[0], hw[1], hw[2], hw[3]);
    *(uint4*)(lo + base) = make_uint4(lw[0], lw[1], lw[2], lw[3]);
}

// ======================= 128x128 HMMA bf16x3 GEMM (8 warps, 64x32, 2 CTA/SM) =======================
#define SSTRIDE 40
#define TILE_B (128*SSTRIDE*2)
#define STAGE_B (4*TILE_B)
#define HG_SMEM (2*STAGE_B)

template<int KSPLIT>
__global__ __launch_bounds__(256, 2) void k_hgemm(
    const __nv_bfloat16* __restrict__ Ahi, const __nv_bfloat16* __restrict__ Alo,
    const __nv_bfloat16* __restrict__ Bhi, const __nv_bfloat16* __restrict__ Blo,
    float* __restrict__ C,
    int M, int N, int K)
{
    extern __shared__ __align__(128) char smem[];
    uint32_t sbase = smem_u32(smem);
    int tid = threadIdx.x;
    int bm = blockIdx.y*128, bn = blockIdx.x*128;
    int lane = tid & 31, wid = tid >> 5;
    int warp_m = (wid >> 2)*64, warp_n = (wid & 3)*32;

    int Keff = KSPLIT ? (K >> 1) : K;
    int Koff = KSPLIT ? blockIdx.z * Keff : 0;
    if (KSPLIT) C += (size_t)blockIdx.z * M * N;

    const __nv_bfloat16* gsrc[4] = {Ahi, Alo, Bhi, Blo};

    float acc[4][4][4];
    #pragma unroll
    for (int mi=0;mi<4;mi++)
        #pragma unroll
        for (int ni=0;ni<4;ni++)
            #pragma unroll
            for (int q=0;q<4;q++) acc[mi][ni][q]=0.f;

    const int NCK = Keff/32;

    int sub = lane >> 3, r = lane & 7;
    uint32_t aoff = (uint32_t)((warp_m + (sub&1)*8 + r)*(SSTRIDE*2) + (sub>>1)*16);
    uint32_t boff = (uint32_t)((warp_n + (sub>>1)*8 + r)*(SSTRIDE*2) + (sub&1)*16);

    auto load_stage = [&](int kc, int buf){
        if (kc < NCK){
            uint32_t sb = sbase + buf*STAGE_B;
            #pragma unroll
            for (int i = 0; i < 8; i++){
                int tile = i >> 1;
                int within = (i&1)*256 + tid;
                int row = within >> 2, ch = within & 3;
                int grow = ((tile < 2) ? bm : bn) + row;
                const __nv_bfloat16* src = gsrc[tile] + (size_t)grow*K + Koff + kc*32 + ch*8;
                uint32_t dst = sb + tile*TILE_B + row*(SSTRIDE*2) + ch*16;
                CP_ASYNC16(dst, src);
            }
        }
        CP_COMMIT();
    };

    load_stage(0, 0);
    load_stage(1, 1);

    for (int kc = 0; kc < NCK; kc++){
        int buf = kc & 1;
        CP_WAIT(1);
        __syncthreads();

        uint32_t sb = sbase + buf*STAGE_B;
        #pragma unroll
        for (int kk = 0; kk < 32; kk += 16){
            uint32_t bh[2][4], bl[2][4];
            #pragma unroll
            for (int nb = 0; nb < 2; nb++){
                uint32_t bd = sb + 2*TILE_B + boff + (uint32_t)(nb*16*(SSTRIDE*2) + kk*2);
                LDSM4(bh[nb], bd);
                LDSM4(bl[nb], bd + TILE_B);
            }
            #pragma unroll
            for (int mp = 0; mp < 4; mp += 2){
                uint32_t ah[2][4], al[2][4];
                #pragma unroll
                for (int q = 0; q < 2; q++){
                    uint32_t ad = sb + aoff + (uint32_t)((mp+q)*16*(SSTRIDE*2) + kk*2);
                    LDSM4(ah[q], ad);
                    LDSM4(al[q], ad + TILE_B);
                }
                #pragma unroll
                for (int q = 0; q < 2; q++)
                    #pragma unroll
                    for (int nb = 0; nb < 2; nb++)
                        #pragma unroll
                        for (int half = 0; half < 2; half++)
                            mma_bf16(acc[mp+q][nb*2+half], ah[q], &bh[nb][half*2]);
                #pragma unroll
                for (int q = 0; q < 2; q++)
                    #pragma unroll
                    for (int nb = 0; nb < 2; nb++)
                        #pragma unroll
                        for (int half = 0; half < 2; half++)
                            mma_bf16(acc[mp+q][nb*2+half], ah[q], &bl[nb][half*2]);
                #pragma unroll
                for (int q = 0; q < 2; q++)
                    #pragma unroll
                    for (int nb = 0; nb < 2; nb++)
                        #pragma unroll
                        for (int half = 0; half < 2; half++)
                            mma_bf16(acc[mp+q][nb*2+half], al[q], &bh[nb][half*2]);
            }
        }
        __syncthreads();
        load_stage(kc+2, buf);
    }

    int g = lane >> 2, t = lane & 3;
    #pragma unroll
    for (int mi = 0; mi < 4; mi++){
        int r0 = bm + warp_m + mi*16 + g;
        #pragma unroll
        for (int ni = 0; ni < 4; ni++){
            int col = bn + warp_n + ni*8 + 2*t;
            if (col < N){
                *(float2*)(C + (size_t)r0*N + col)     = make_float2(acc[mi][ni][0], acc[mi][ni][1]);
                *(float2*)(C + (size_t)(r0+8)*N + col) = make_float2(acc[mi][ni][2], acc[mi][ni][3]);
            }
        }
    }
}

// ---------------- fused embedding gather + rmsnorm + split ----------------
__global__ void k_embednorm(const int* __restrict__ ids, const float* __restrict__ emb,
                            const float* __restrict__ w,
                            __nv_bfloat16* __restrict__ hi, __nv_bfloat16* __restrict__ lo){
    int t = blockIdx.x, tid = threadIdx.x;
    int row = ids[t];
    __shared__ float buf[DMODEL];
    __shared__ float red[256];
    float ss = 0.f;
    for (int d = tid; d < DMODEL; d += 256){
        float v = emb[(size_t)row*DMODEL + d];
        g_x[(size_t)t*DMODEL + d] = v;
        buf[d] = v;
        ss += v*v;
    }
    red[tid] = ss; __syncthreads();
    for (int o = 128; o > 0; o >>= 1){ if (tid < o) red[tid] += red[tid+o]; __syncthreads(); }
    float sc = rsqrtf(red[0]/(float)DMODEL + 1e-6f);
    for (int d = tid*2; d < DMODEL; d += 512){
        float v0 = buf[d]*sc*w[d];
        float v1 = buf[d+1]*sc*w[d+1];
        uint32_t hw, lw; split2(v0, v1, hw, lw);
        *(uint32_t*)(hi + (size_t)t*DMODEL + d) = hw;
        *(uint32_t*)(lo + (size_t)t*DMODEL + d) = lw;
    }
}

// ---------------- fused residual add + rmsnorm + split ----------------
__global__ void k_addnorm(const float* __restrict__ c0, const float* __restrict__ c1,
                          const float* __restrict__ w,
                          __nv_bfloat16* __restrict__ hi, __nv_bfloat16* __restrict__ lo){
    int t = blockIdx.x, tid = threadIdx.x;
    __shared__ float buf[DMODEL];
    __shared__ float red[256];
    float ss = 0.f;
    for (int d = tid; d < DMODEL; d += 256){
        size_t idx = (size_t)t*DMODEL + d;
        float v = g_x[idx] + c0[idx] + c1[idx];
        g_x[idx] = v;
        buf[d] = v;
        ss += v*v;
    }
    red[tid] = ss; __syncthreads();
    for (int o = 128; o > 0; o >>= 1){ if (tid < o) red[tid] += red[tid+o]; __syncthreads(); }
    float sc = rsqrtf(red[0]/(float)DMODEL + 1e-6f);
    for (int d = tid*2; d < DMODEL; d += 512){
        float v0 = buf[d]*sc*w[d];
        float v1 = buf[d+1]*sc*w[d+1];
        uint32_t hw, lw; split2(v0, v1, hw, lw);
        *(uint32_t*)(hi + (size_t)t*DMODEL + d) = hw;
        *(uint32_t*)(lo + (size_t)t*DMODEL + d) = lw;
    }
}

// ---------------- gated rmsnorm -> bf16 hi/lo ----------------
__global__ void k_gatenorm_split(const float* __restrict__ gw,
                                 __nv_bfloat16* __restrict__ hi, __nv_bfloat16* __restrict__ lo){
    int t = blockIdx.x, tid = threadIdx.x;
    __shared__ float v[DINNER];
    __shared__ float red[256];
    float ss = 0.f;
    for (int d = tid; d < DINNER; d += 256){
        float z = g_zx[(size_t)t*DINPROJ + d];
        float sil = z / (1.f + __expf(-z));
        float val = g_y[(size_t)t*DINNER + d] * sil;
        v[d] = val; ss += val*val;
    }
    red[tid] = ss; __syncthreads();
    for (int o = 128; o > 0; o >>= 1){ if (tid < o) red[tid] += red[tid+o]; __syncthreads(); }
    float sc = rsqrtf(red[0]/(float)DINNER + 1e-5f);
    for (int d = tid*2; d < DINNER; d += 512){
        float v0 = v[d]*sc*gw[d];
        float v1 = v[d+1]*sc*gw[d+1];
        uint32_t hw, lw; split2(v0, v1, hw, lw);
        *(uint32_t*)(hi + (size_t)t*DINNER + d) = hw;
        *(uint32_t*)(lo + (size_t)t*DINNER + d) = lw;
    }
}

// ---------------- fused conv+silu | dt+cumsum ----------------
__global__ void k_convcum(const float* __restrict__ cw, const float* __restrict__ cb,
                          const float* __restrict__ A_log, const float* __restrict__ dtb){
    int b = blockIdx.x, tid = threadIdx.x;
    if (b < CONVBLOCKS){
        int idx = b*256 + tid;
        int t = idx / CONVDIM, ch = idx % CONVDIM;
        float acc = cb[ch];
        #pragma unroll
        for (int k = 0; k < 4; k++){
            int tt = t - 3 + k;
            if (tt >= 0) acc += cw[ch*4 + k] * g_zx[(size_t)tt*DINPROJ + DINNER + ch];
        }
        g_xBC[idx] = acc / (1.f + __expf(-acc));
    } else {
        int bb = b - CONVBLOCKS;
        int h = bb % NHEADS, c = bb / NHEADS;
        float A = -__expf(A_log[h]);
        __shared__ float s[CHUNK];
        int tg = c*CHUNK + tid;
        float x = g_zx[(size_t)tg*DINPROJ + DINNER + CONVDIM + h] + dtb[h];
        float dtv = (x > 20.f) ? x : log1pf(__expf(x));
        g_dt[(size_t)tg*NHEADS + h] = dtv;
        float v = dtv * A;
        s[tid] = v; __syncthreads();
        for (int o = 1; o < CHUNK; o <<= 1){
            float add = (tid >= o) ? s[tid - o] : 0.f;
            __syncthreads();
            s[tid] += add;
            __syncthreads();
        }
        g_acum[(size_t)h*SEQ + c*CHUNK + tid] = s[tid];
    }
}

// ---------------- fused G | states ----------------
__global__ __launch_bounds__(256) void k_Gstates(){
    __shared__ __align__(16) float sh[4096];
    int b = blockIdx.x, tid = threadIdx.x;
    if (b < 128){
        int c = b >> 4, rest = b & 15;
        int s0 = (rest >> 2)*64, l0 = (rest & 3)*64;
        float (*Bs)[64] = (float(*)[64])sh;
        float (*Cs)[64] = (float(*)[64])(sh + 1024);
        int ty = tid/16, tx = tid%16;
        int lr = tid/4, lk = (tid%4)*4;
        float acc[4][4];
        #pragma unroll
        for (int i=0;i<4;i++)
            #pragma unroll
            for (int j=0;j<4;j++) acc[i][j]=0.f;
        const float* base = g_xBC + (size_t)(c*CHUNK)*CONVDIM;
        for (int k0 = 0; k0 < DSTATE; k0 += 16){
            __syncthreads();
            float4 b4 = *(const float4*)(base + (size_t)(s0+lr)*CONVDIM + DINNER + k0 + lk);
            float4 c4 = *(const float4*)(base + (size_t)(l0+lr)*CONVDIM + DINNER + DSTATE + k0 + lk);
            Bs[lk+0][lr]=b4.x; Bs[lk+1][lr]=b4.y; Bs[lk+2][lr]=b4.z; Bs[lk+3][lr]=b4.w;
            Cs[lk+0][lr]=c4.x; Cs[lk+1][lr]=c4.y; Cs[lk+2][lr]=c4.z; Cs[lk+3][lr]=c4.w;
            __syncthreads();
            #pragma unroll
            for (int k = 0; k < 16; k++){
                float a[4], bb[4];
                #pragma unroll
                for (int i=0;i<4;i++) a[i] = Bs[k][ty*4+i];
                #pragma unroll
                for (int j=0;j<4;j++) bb[j] = Cs[k][tx*4+j];
                #pragma unroll
                for (int i=0;i<4;i++)
                    #pragma unroll
                    for (int j=0;j<4;j++) acc[i][j] += a[i]*bb[j];
            }
        }
        #pragma unroll
        for (int i=0;i<4;i++){
            int sidx = s0 + ty*4 + i;
            #pragma unroll
            for (int j=0;j<4;j++)
                g_G[(size_t)c*CHUNK*CHUNK + (size_t)sidx*CHUNK + (l0 + tx*4 + j)] = acc[i][j];
        }
    } else {
        int bb = b - 128;
        int c = bb & 7, h = bb >> 3;
        float* sB = sh;
        float* sX = sh + 2048;
        int pi = tid >> 2, ng = tid & 3;
        float acc[16];
        #pragma unroll
        for (int i=0;i<16;i++) acc[i]=0.f;
        const float* acum = g_acum + (size_t)h*SEQ + c*CHUNK;
        float alast = acum[CHUNK-1];
        for (int s0 = 0; s0 < CHUNK; s0 += 32){
            __syncthreads();
            #pragma unroll
            for (int i = 0; i < 8; i++){
                int idx = i*256 + tid; int ssi = idx>>6, n = idx&63;
                int t = c*CHUNK + s0 + ssi;
                sB[idx] = g_xBC[(size_t)t*CONVDIM + DINNER + n];
                float d  = g_dt[(size_t)t*NHEADS + h];
                float dec = __expf(alast - acum[s0+ssi]);
                sX[idx] = g_xBC[(size_t)t*CONVDIM + h*HEADDIM + n] * d * dec;
            }
            __syncthreads();
            for (int ssi = 0; ssi < 32; ssi++){
                float xv = sX[ssi*64 + pi];
                const float4* b4p = (const float4*)(sB + ssi*64 + ng*16);
                #pragma unroll
                for (int j = 0; j < 4; j++){
                    float4 bv = b4p[j];
                    acc[j*4+0] += xv*bv.x; acc[j*4+1] += xv*bv.y;
                    acc[j*4+2] += xv*bv.z; acc[j*4+3] += xv*bv.w;
                }
            }
        }
        float* out = g_S + (size_t)(c*NHEADS + h)*HEADDIM*DSTATE + pi*DSTATE + ng*16;
        #pragma unroll
        for (int j = 0; j < 4; j++)
            *(float4*)(out + j*4) = make_float4(acc[j*4+0], acc[j*4+1], acc[j*4+2], acc[j*4+3]);
    }
}

// ---------------- fused recurrence + Y_off + Y_diag ----------------
// grid (NCHUNK, NHEADS); builds prev[c,h] in smem from S chunks directly.
__global__ __launch_bounds__(256) void k_yoffy(const float* __restrict__ Dskip){
    int c = blockIdx.x, h = blockIdx.y;
    __shared__ __align__(16) float sbuf[4096];
    __shared__ float sac[CHUNK];
    int tid = threadIdx.x, l = tid;
    sac[tid] = g_acum[(size_t)h*SEQ + c*CHUNK + tid];
    // build prev state in smem: prev = sum_{c'<c} S[c'] * prod_{j=c'+1}^{c-1} dec[j]
    #pragma unroll
    for (int i = 0; i < 16; i++) sbuf[i*256 + tid] = 0.f;
    float w = 1.f;
    for (int cp = c - 1; cp >= 0; cp--){
        size_t base = (size_t)(cp*NHEADS + h)*HEADDIM*DSTATE;
        #pragma unroll
        for (int i = 0; i < 16; i++)
            sbuf[i*256 + tid] += w * g_S[base + i*256 + tid];
        w *= __expf(g_acum[(size_t)h*SEQ + cp*CHUNK + CHUNK-1]);
    }
    __syncthreads();
    float aL = sac[l];
    float eL = __expf(aL);
    float acc[64];
    {
        const float4* Crow = (const float4*)(g_xBC + (size_t)(c*CHUNK + l)*CONVDIM + DINNER + DSTATE);
        float4 cr[16];
        #pragma unroll
        for (int i = 0; i < 16; i++) cr[i] = Crow[i];
        const float4* ps4 = (const float4*)sbuf;
        for (int p = 0; p < HEADDIM; p++){
            float s = 0.f;
            #pragma unroll
            for (int i = 0; i < 16; i++){
                float4 bv = ps4[p*16 + i];
                s += cr[i].x*bv.x + cr[i].y*bv.y + cr[i].z*bv.z + cr[i].w*bv.w;
            }
            acc[p] = eL*s;
        }
    }
    const float* Gt = g_G + (size_t)c*CHUNK*CHUNK;
    float* sX = sbuf;
    for (int s0 = 0; s0 < CHUNK; s0 += 32){
        __syncthreads();
        #pragma unroll
        for (int i = 0; i < 8; i++){
            int idx = i*256 + tid; int ssi = idx>>6, p = idx&63;
            int t = c*CHUNK + s0 + ssi;
            sX[idx] = g_xBC[(size_t)t*CONVDIM + h*HEADDIM + p] * g_dt[(size_t)t*NHEADS + h];
        }
        __syncthreads();
        int smax = l - s0 + 1; if (smax > 32) smax = 32;
        for (int ssi = 0; ssi < smax; ssi++){
            int s = s0 + ssi;
            float g = Gt[(size_t)s*CHUNK + l] * __expf(aL - sac[s]);
            const float4* x4 = (const float4*)(sX + ssi*64);
            #pragma unroll
            for (int p = 0; p < 16; p++){
                float4 xv = x4[p];
                acc[p*4+0] += g*xv.x; acc[p*4+1] += g*xv.y;
                acc[p*4+2] += g*xv.z; acc[p*4+3] += g*xv.w;
            }
        }
    }
    float dsk = Dskip[h];
    int t = c*CHUNK + l;
    float* yo = g_y + (size_t)t*DINNER + h*HEADDIM;
    const float* xr = g_xBC + (size_t)t*CONVDIM + h*HEADDIM;
    #pragma unroll
    for (int p = 0; p < 64; p++) yo[p] = acc[p] + dsk*xr[p];
}

// ---------------- host orchestration ----------------
extern "C" void kernel_launch(void* const* d_in, const int* in_sizes, int n_in,
                              void* d_out, int out_size){
    const int*   ids     = (const int*)  d_in[0];
    const float* emb     = (const float*)d_in[1];
    const float* ln_w    = (const float*)d_in[2];
    const float* in_w    = (const float*)d_in[3];
    const float* conv_w  = (const float*)d_in[4];
    const float* conv_b  = (const float*)d_in[5];
    const float* dt_b    = (const float*)d_in[6];
    const float* A_log   = (const float*)d_in[7];
    const float* D_skip  = (const float*)d_in[8];
    const float* gnorm_w = (const float*)d_in[9];
    const float* out_w   = (const float*)d_in[10];
    const float* norm_f  = (const float*)d_in[11];
    float* out = (float*)d_out;

    float *px, *pzx;
    __nv_bfloat16 *pahi, *palo, *pbhi, *pblo, *pwihi, *pwilo, *pwohi, *pwolo;
    cudaGetSymbolAddress((void**)&px,  g_x);
    cudaGetSymbolAddress((void**)&pzx, g_zx);
    cudaGetSymbolAddress((void**)&pahi, g_ahi);
    cudaGetSymbolAddress((void**)&palo, g_alo);
    cudaGetSymbolAddress((void**)&pbhi, g_bhi);
    cudaGetSymbolAddress((void**)&pblo, g_blo);
    cudaGetSymbolAddress((void**)&pwihi, g_wihi);
    cudaGetSymbolAddress((void**)&pwilo, g_wilo);
    cudaGetSymbolAddress((void**)&pwohi, g_wohi);
    cudaGetSymbolAddress((void**)&pwolo, g_wolo);

    cudaFuncSetAttribute(k_hgemm<0>, cudaFuncAttributeMaxDynamicSharedMemorySize, HG_SMEM);
    cudaFuncSetAttribute(k_hgemm<1>, cudaFuncAttributeMaxDynamicSharedMemorySize, HG_SMEM);

    // ---- prologue: all weight splits (constant data) ----
    k_wsplit_inw<<<(NLAYER*DINPROJ_PAD*DMODEL/8 + 255)/256, 256>>>(in_w, pwihi, pwilo);
    k_wsplit<<<(NLAYER*DMODEL*DINNER/8 + 255)/256, 256>>>(out_w, pwohi, pwolo,
                                                          NLAYER*DMODEL*DINNER, NLAYER*DMODEL*DINNER);
    k_wsplit<<<(VOCAB*DMODEL/8 + 255)/256, 256>>>(emb, pbhi, pblo, VOCAB*DMODEL, VOCAB*DMODEL);

    k_embednorm<<<SEQ, 256>>>(ids, emb, ln_w, pahi, palo);
    for (int i = 0; i < NLAYER; i++){
        k_hgemm<0><<<dim3(DINPROJ_PAD/128, SEQ/128), 256, HG_SMEM>>>(
            pahi, palo,
            pwihi + (size_t)i*DINPROJ_PAD*DMODEL, pwilo + (size_t)i*DINPROJ_PAD*DMODEL,
            pzx, SEQ, DINPROJ, DMODEL);

        k_convcum<<<CONVBLOCKS + NHEADS*NCHUNK, 256>>>(conv_w + (size_t)i*CONVDIM*4,
                                                       conv_b + i*CONVDIM,
                                                       A_log + i*NHEADS, dt_b + i*NHEADS);
        k_Gstates<<<128 + NCHUNK*NHEADS, 256>>>();
        k_yoffy<<<dim3(NCHUNK, NHEADS), 256>>>(D_skip + i*NHEADS);
        k_gatenorm_split<<<SEQ, 256>>>(gnorm_w + (size_t)i*DINNER, pahi, palo);

        k_hgemm<1><<<dim3(DMODEL/128, SEQ/128, 2), 256, HG_SMEM>>>(
            pahi, palo,
            pwohi + (size_t)i*DMODEL*DINNER, pwolo + (size_t)i*DMODEL*DINNER,
            pzx, SEQ, DMODEL, DINNER);
        const float* wnext = (i + 1 < NLAYER) ? (ln_w + (size_t)(i+1)*DMODEL) : norm_f;
        k_addnorm<<<SEQ, 256>>>(pzx, pzx + SEQ*DMODEL, wnext, pahi, palo);
    }
    k_hgemm<0><<<dim3(VOCAB/128, SEQ/128), 256, HG_SMEM>>>(
        pahi, palo, pbhi, pblo, out, SEQ, VOCAB, DMODEL);
}

// round 16
// speedup vs baseline: 1.0093x; 1.0061x over previous
#include <cuda_runtime.h>
#include <cuda_bf16.h>
#include <math.h>
#include <stdint.h>

#define SEQ     2048
#define DMODEL  768
#define NLAYER  16
#define DSTATE  64
#define HEADDIM 64
#define DINNER  1536
#define NHEADS  24
#define CONVDIM 1664
#define DINPROJ 3224
#define DINPROJ_PAD 3328
#define CHUNK   256
#define NCHUNK  8
#define VOCAB   32000
#define CONVBLOCKS (SEQ*CONVDIM/256)   // 13312

// ---------------- scratch ----------------
__device__ float g_x  [SEQ*DMODEL];
__device__ float g_zx [SEQ*DINPROJ];     // also reused as out_proj split-K partial buffers
__device__ float g_xBC[SEQ*CONVDIM];
__device__ float g_dt [SEQ*NHEADS];
__device__ float g_acum[NHEADS*SEQ];
__device__ float g_G  [NCHUNK*CHUNK*CHUNK];
__device__ float g_S  [NCHUNK*NHEADS*HEADDIM*DSTATE];
__device__ float g_prev[NCHUNK*NHEADS*HEADDIM*DSTATE];
__device__ float g_y  [SEQ*DINNER];

// activation planes
__device__ __align__(16) __nv_bfloat16 g_ahi[SEQ*DINNER];
__device__ __align__(16) __nv_bfloat16 g_alo[SEQ*DINNER];
// vocab/emb planes
__device__ __align__(16) __nv_bfloat16 g_bhi[VOCAB*DMODEL];
__device__ __align__(16) __nv_bfloat16 g_blo[VOCAB*DMODEL];
// per-layer weight planes (precomputed once per launch)
__device__ __align__(16) __nv_bfloat16 g_wihi[NLAYER*DINPROJ_PAD*DMODEL];
__device__ __align__(16) __nv_bfloat16 g_wilo[NLAYER*DINPROJ_PAD*DMODEL];
__device__ __align__(16) __nv_bfloat16 g_wohi[NLAYER*DMODEL*DINNER];
__device__ __align__(16) __nv_bfloat16 g_wolo[NLAYER*DMODEL*DINNER];

// ======================= PTX helpers =======================
__device__ __forceinline__ uint32_t smem_u32(const void* p){
    uint32_t a; asm("{ .reg .u64 t; cvta.to.shared.u64 t, %1; cvt.u32.u64 %0, t; }" : "=r"(a) : "l"(p));
    return a;
}
#define CP_ASYNC16(dst, src) \
    asm volatile("cp.async.cg.shared.global [%0], [%1], 16;" :: "r"(dst), "l"(src))
#define CP_COMMIT() asm volatile("cp.async.commit_group;" ::: "memory")
#define CP_WAIT(n)  asm volatile("cp.async.wait_group %0;" :: "n"(n) : "memory")

#define LDSM4(r, addr) \
    asm volatile("ldmatrix.sync.aligned.m8n8.x4.shared.b16 {%0,%1,%2,%3}, [%4];" \
        : "=r"((r)[0]), "=r"((r)[1]), "=r"((r)[2]), "=r"((r)[3]) : "r"(addr))

__device__ __forceinline__ void mma_bf16(float* c, const uint32_t* a, const uint32_t* b){
    asm volatile("mma.sync.aligned.m16n8k16.row.col.f32.bf16.bf16.f32 "
        "{%0,%1,%2,%3}, {%4,%5,%6,%7}, {%8,%9}, {%0,%1,%2,%3};"
        : "+f"(c[0]), "+f"(c[1]), "+f"(c[2]), "+f"(c[3])
        : "r"(a[0]), "r"(a[1]), "r"(a[2]), "r"(a[3]), "r"(b[0]), "r"(b[1]));
}

__device__ __forceinline__ void split2(float v0, float v1, uint32_t& hw, uint32_t& lw){
    __nv_bfloat162 h = __floats2bfloat162_rn(v0, v1);
    hw = *reinterpret_cast<uint32_t*>(&h);
    __nv_bfloat162 l = __floats2bfloat162_rn(v0 - __bfloat162float(h.x), v1 - __bfloat162float(h.y));
    lw = *reinterpret_cast<uint32_t*>(&l);
}

// ---------------- vectorized weight split (contiguous) ----------------
__global__ void k_wsplit(const float* __restrict__ src, __nv_bfloat16* __restrict__ hi,
                         __nv_bfloat16* __restrict__ lo, int n, int npad){
    int base = (blockIdx.x*256 + threadIdx.x)*8;
    if (base >= npad) return;
    float v[8];
    if (base + 8 <= n){
        float4 a0 = *(const float4*)(src + base);
        float4 a1 = *(const float4*)(src + base + 4);
        v[0]=a0.x; v[1]=a0.y; v[2]=a0.z; v[3]=a0.w;
        v[4]=a1.x; v[5]=a1.y; v[6]=a1.z; v[7]=a1.w;
    } else {
        #pragma unroll
        for (int i = 0; i < 8; i++) v[i] = (base + i < n) ? src[base+i] : 0.f;
    }
    uint32_t hw[4], lw[4];
    #pragma unroll
    for (int i = 0; i < 4; i++) split2(v[2*i], v[2*i+1], hw[i], lw[i]);
    *(uint4*)(hi + base) = make_uint4(hw[0], hw[1], hw[2], hw[3]);
    *(uint4*)(lo + base) = make_uint4(lw[0], lw[1], lw[2], lw[3]);
}

// ---------------- in_w split with per-layer N padding (3224 -> 3328 rows) ----------------
__global__ void k_wsplit_inw(const float* __restrict__ src,
                             __nv_bfloat16* __restrict__ hi, __nv_bfloat16* __restrict__ lo){
    int base = (blockIdx.x*256 + threadIdx.x)*8;
    if (base >= NLAYER*DINPROJ_PAD*DMODEL) return;
    int layer = base / (DINPROJ_PAD*DMODEL);
    int rem   = base % (DINPROJ_PAD*DMODEL);
    int row   = rem / DMODEL;
    int col   = rem % DMODEL;
    float v[8];
    if (row < DINPROJ){
        const float* s = src + (size_t)layer*DINPROJ*DMODEL + (size_t)row*DMODEL + col;
        float4 a0 = *(const float4*)s;
        float4 a1 = *(const float4*)(s + 4);
        v[0]=a0.x; v[1]=a0.y; v[2]=a0.z; v[3]=a0.w;
        v[4]=a1.x; v[5]=a1.y; v[6]=a1.z; v[7]=a1.w;
    } else {
        #pragma unroll
        for (int i = 0; i < 8; i++) v[i] = 0.f;
    }
    uint32_t hw[4], lw[4];
    #pragma unroll
    for (int i = 0; i < 4; i++) split2(v[2*i], v[2*i+1], hw[i], lw[i]);
    *(uint4*)(hi + base) = make_uint4(hw[0], hw[1], hw[2], hw[3]);
    *(uint4*)(lo + base) = make_uint4(lw[0], lw[1], lw[2], lw[3]);
}

// ======================= 128x128 HMMA bf16x3 GEMM (8 warps, 64x32, 2 CTA/SM) =======================
#define SSTRIDE 40
#define TILE_B (128*SSTRIDE*2)
#define STAGE_B (4*TILE_B)
#define HG_SMEM (2*STAGE_B)

template<int KSPLIT>
__global__ __launch_bounds__(256, 2) void k_hgemm(
    const __nv_bfloat16* __restrict__ Ahi, const __nv_bfloat16* __restrict__ Alo,
    const __nv_bfloat16* __restrict__ Bhi, const __nv_bfloat16* __restrict__ Blo,
    float* __restrict__ C,
    int M, int N, int K)
{
    extern __shared__ __align__(128) char smem[];
    uint32_t sbase = smem_u32(smem);
    int tid = threadIdx.x;
    int bm = blockIdx.y*128, bn = blockIdx.x*128;
    int lane = tid & 31, wid = tid >> 5;
    int warp_m = (wid >> 2)*64, warp_n = (wid & 3)*32;

    int Keff = KSPLIT ? (K >> 1) : K;
    int Koff = KSPLIT ? blockIdx.z * Keff : 0;
    if (KSPLIT) C += (size_t)blockIdx.z * M * N;

    const __nv_bfloat16* gsrc[4] = {Ahi, Alo, Bhi, Blo};

    float acc[4][4][4];
    #pragma unroll
    for (int mi=0;mi<4;mi++)
        #pragma unroll
        for (int ni=0;ni<4;ni++)
            #pragma unroll
            for (int q=0;q<4;q++) acc[mi][ni][q]=0.f;

    const int NCK = Keff/32;

    int sub = lane >> 3, r = lane & 7;
    uint32_t aoff = (uint32_t)((warp_m + (sub&1)*8 + r)*(SSTRIDE*2) + (sub>>1)*16);
    uint32_t boff = (uint32_t)((warp_n + (sub>>1)*8 + r)*(SSTRIDE*2) + (sub&1)*16);

    auto load_stage = [&](int kc, int buf){
        if (kc < NCK){
            uint32_t sb = sbase + buf*STAGE_B;
            #pragma unroll
            for (int i = 0; i < 8; i++){
                int tile = i >> 1;
                int within = (i&1)*256 + tid;
                int row = within >> 2, ch = within & 3;
                int grow = ((tile < 2) ? bm : bn) + row;
                const __nv_bfloat16* src = gsrc[tile] + (size_t)grow*K + Koff + kc*32 + ch*8;
                uint32_t dst = sb + tile*TILE_B + row*(SSTRIDE*2) + ch*16;
                CP_ASYNC16(dst, src);
            }
        }
        CP_COMMIT();
    };

    load_stage(0, 0);
    load_stage(1, 1);

    for (int kc = 0; kc < NCK; kc++){
        int buf = kc & 1;
        CP_WAIT(1);
        __syncthreads();

        uint32_t sb = sbase + buf*STAGE_B;
        #pragma unroll
        for (int kk = 0; kk < 32; kk += 16){
            uint32_t bh[2][4], bl[2][4];
            #pragma unroll
            for (int nb = 0; nb < 2; nb++){
                uint32_t bd = sb + 2*TILE_B + boff + (uint32_t)(nb*16*(SSTRIDE*2) + kk*2);
                LDSM4(bh[nb], bd);
                LDSM4(bl[nb], bd + TILE_B);
            }
            #pragma unroll
            for (int mp = 0; mp < 4; mp += 2){
                uint32_t ah[2][4], al[2][4];
                #pragma unroll
                for (int q = 0; q < 2; q++){
                    uint32_t ad = sb + aoff + (uint32_t)((mp+q)*16*(SSTRIDE*2) + kk*2);
                    LDSM4(ah[q], ad);
                    LDSM4(al[q], ad + TILE_B);
                }
                #pragma unroll
                for (int q = 0; q < 2; q++)
                    #pragma unroll
                    for (int nb = 0; nb < 2; nb++)
                        #pragma unroll
                        for (int half = 0; half < 2; half++)
                            mma_bf16(acc[mp+q][nb*2+half], ah[q], &bh[nb][half*2]);
                #pragma unroll
                for (int q = 0; q < 2; q++)
                    #pragma unroll
                    for (int nb = 0; nb < 2; nb++)
                        #pragma unroll
                        for (int half = 0; half < 2; half++)
                            mma_bf16(acc[mp+q][nb*2+half], ah[q], &bl[nb][half*2]);
                #pragma unroll
                for (int q = 0; q < 2; q++)
                    #pragma unroll
                    for (int nb = 0; nb < 2; nb++)
                        #pragma unroll
                        for (int half = 0; half < 2; half++)
                            mma_bf16(acc[mp+q][nb*2+half], al[q], &bh[nb][half*2]);
            }
        }
        __syncthreads();
        load_stage(kc+2, buf);
    }

    int g = lane >> 2, t = lane & 3;
    #pragma unroll
    for (int mi = 0; mi < 4; mi++){
        int r0 = bm + warp_m + mi*16 + g;
        #pragma unroll
        for (int ni = 0; ni < 4; ni++){
            int col = bn + warp_n + ni*8 + 2*t;
            if (col < N){
                *(float2*)(C + (size_t)r0*N + col)     = make_float2(acc[mi][ni][0], acc[mi][ni][1]);
                *(float2*)(C + (size_t)(r0+8)*N + col) = make_float2(acc[mi][ni][2], acc[mi][ni][3]);
            }
        }
    }
}

// ---------------- fused embedding gather + rmsnorm + split ----------------
__global__ void k_embednorm(const int* __restrict__ ids, const float* __restrict__ emb,
                            const float* __restrict__ w,
                            __nv_bfloat16* __restrict__ hi, __nv_bfloat16* __restrict__ lo){
    int t = blockIdx.x, tid = threadIdx.x;
    int row = ids[t];
    __shared__ float buf[DMODEL];
    __shared__ float red[256];
    float ss = 0.f;
    for (int d = tid; d < DMODEL; d += 256){
        float v = emb[(size_t)row*DMODEL + d];
        g_x[(size_t)t*DMODEL + d] = v;
        buf[d] = v;
        ss += v*v;
    }
    red[tid] = ss; __syncthreads();
    for (int o = 128; o > 0; o >>= 1){ if (tid < o) red[tid] += red[tid+o]; __syncthreads(); }
    float sc = rsqrtf(red[0]/(float)DMODEL + 1e-6f);
    for (int d = tid*2; d < DMODEL; d += 512){
        float v0 = buf[d]*sc*w[d];
        float v1 = buf[d+1]*sc*w[d+1];
        uint32_t hw, lw; split2(v0, v1, hw, lw);
        *(uint32_t*)(hi + (size_t)t*DMODEL + d) = hw;
        *(uint32_t*)(lo + (size_t)t*DMODEL + d) = lw;
    }
}

// ---------------- fused residual add + rmsnorm + split ----------------
__global__ void k_addnorm(const float* __restrict__ c0, const float* __restrict__ c1,
                          const float* __restrict__ w,
                          __nv_bfloat16* __restrict__ hi, __nv_bfloat16* __restrict__ lo){
    int t = blockIdx.x, tid = threadIdx.x;
    __shared__ float buf[DMODEL];
    __shared__ float red[256];
    float ss = 0.f;
    for (int d = tid; d < DMODEL; d += 256){
        size_t idx = (size_t)t*DMODEL + d;
        float v = g_x[idx] + c0[idx] + c1[idx];
        g_x[idx] = v;
        buf[d] = v;
        ss += v*v;
    }
    red[tid] = ss; __syncthreads();
    for (int o = 128; o > 0; o >>= 1){ if (tid < o) red[tid] += red[tid+o]; __syncthreads(); }
    float sc = rsqrtf(red[0]/(float)DMODEL + 1e-6f);
    for (int d = tid*2; d < DMODEL; d += 512){
        float v0 = buf[d]*sc*w[d];
        float v1 = buf[d+1]*sc*w[d+1];
        uint32_t hw, lw; split2(v0, v1, hw, lw);
        *(uint32_t*)(hi + (size_t)t*DMODEL + d) = hw;
        *(uint32_t*)(lo + (size_t)t*DMODEL + d) = lw;
    }
}

// ---------------- gated rmsnorm -> bf16 hi/lo ----------------
__global__ void k_gatenorm_split(const float* __restrict__ gw,
                                 __nv_bfloat16* __restrict__ hi, __nv_bfloat16* __restrict__ lo){
    int t = blockIdx.x, tid = threadIdx.x;
    __shared__ float v[DINNER];
    __shared__ float red[256];
    float ss = 0.f;
    for (int d = tid; d < DINNER; d += 256){
        float z = g_zx[(size_t)t*DINPROJ + d];
        float sil = z / (1.f + __expf(-z));
        float val = g_y[(size_t)t*DINNER + d] * sil;
        v[d] = val; ss += val*val;
    }
    red[tid] = ss; __syncthreads();
    for (int o = 128; o > 0; o >>= 1){ if (tid < o) red[tid] += red[tid+o]; __syncthreads(); }
    float sc = rsqrtf(red[0]/(float)DINNER + 1e-5f);
    for (int d = tid*2; d < DINNER; d += 512){
        float v0 = v[d]*sc*gw[d];
        float v1 = v[d+1]*sc*gw[d+1];
        uint32_t hw, lw; split2(v0, v1, hw, lw);
        *(uint32_t*)(hi + (size_t)t*DINNER + d) = hw;
        *(uint32_t*)(lo + (size_t)t*DINNER + d) = lw;
    }
}

// ---------------- fused conv+silu | dt+cumsum ----------------
__global__ void k_convcum(const float* __restrict__ cw, const float* __restrict__ cb,
                          const float* __restrict__ A_log, const float* __restrict__ dtb){
    int b = blockIdx.x, tid = threadIdx.x;
    if (b < CONVBLOCKS){
        int idx = b*256 + tid;
        int t = idx / CONVDIM, ch = idx % CONVDIM;
        float acc = cb[ch];
        #pragma unroll
        for (int k = 0; k < 4; k++){
            int tt = t - 3 + k;
            if (tt >= 0) acc += cw[ch*4 + k] * g_zx[(size_t)tt*DINPROJ + DINNER + ch];
        }
        g_xBC[idx] = acc / (1.f + __expf(-acc));
    } else {
        int bb = b - CONVBLOCKS;
        int h = bb % NHEADS, c = bb / NHEADS;
        float A = -__expf(A_log[h]);
        __shared__ float s[CHUNK];
        int tg = c*CHUNK + tid;
        float x = g_zx[(size_t)tg*DINPROJ + DINNER + CONVDIM + h] + dtb[h];
        float dtv = (x > 20.f) ? x : log1pf(__expf(x));
        g_dt[(size_t)tg*NHEADS + h] = dtv;
        float v = dtv * A;
        s[tid] = v; __syncthreads();
        for (int o = 1; o < CHUNK; o <<= 1){
            float add = (tid >= o) ? s[tid - o] : 0.f;
            __syncthreads();
            s[tid] += add;
            __syncthreads();
        }
        g_acum[(size_t)h*SEQ + c*CHUNK + tid] = s[tid];
    }
}

// ---------------- fused G | states ----------------
__global__ __launch_bounds__(256) void k_Gstates(){
    __shared__ __align__(16) float sh[4096];
    int b = blockIdx.x, tid = threadIdx.x;
    if (b < 128){
        int c = b >> 4, rest = b & 15;
        int s0 = (rest >> 2)*64, l0 = (rest & 3)*64;
        float (*Bs)[64] = (float(*)[64])sh;
        float (*Cs)[64] = (float(*)[64])(sh + 1024);
        int ty = tid/16, tx = tid%16;
        int lr = tid/4, lk = (tid%4)*4;
        float acc[4][4];
        #pragma unroll
        for (int i=0;i<4;i++)
            #pragma unroll
            for (int j=0;j<4;j++) acc[i][j]=0.f;
        const float* base = g_xBC + (size_t)(c*CHUNK)*CONVDIM;
        for (int k0 = 0; k0 < DSTATE; k0 += 16){
            __syncthreads();
            float4 b4 = *(const float4*)(base + (size_t)(s0+lr)*CONVDIM + DINNER + k0 + lk);
            float4 c4 = *(const float4*)(base + (size_t)(l0+lr)*CONVDIM + DINNER + DSTATE + k0 + lk);
            Bs[lk+0][lr]=b4.x; Bs[lk+1][lr]=b4.y; Bs[lk+2][lr]=b4.z; Bs[lk+3][lr]=b4.w;
            Cs[lk+0][lr]=c4.x; Cs[lk+1][lr]=c4.y; Cs[lk+2][lr]=c4.z; Cs[lk+3][lr]=c4.w;
            __syncthreads();
            #pragma unroll
            for (int k = 0; k < 16; k++){
                float a[4], bb[4];
                #pragma unroll
                for (int i=0;i<4;i++) a[i] = Bs[k][ty*4+i];
                #pragma unroll
                for (int j=0;j<4;j++) bb[j] = Cs[k][tx*4+j];
                #pragma unroll
                for (int i=0;i<4;i++)
                    #pragma unroll
                    for (int j=0;j<4;j++) acc[i][j] += a[i]*bb[j];
            }
        }
        #pragma unroll
        for (int i=0;i<4;i++){
            int sidx = s0 + ty*4 + i;
            #pragma unroll
            for (int j=0;j<4;j++)
                g_G[(size_t)c*CHUNK*CHUNK + (size_t)sidx*CHUNK + (l0 + tx*4 + j)] = acc[i][j];
        }
    } else {
        int bb = b - 128;
        int c = bb & 7, h = bb >> 3;
        float* sB = sh;
        float* sX = sh + 2048;
        int pi = tid >> 2, ng = tid & 3;
        float acc[16];
        #pragma unroll
        for (int i=0;i<16;i++) acc[i]=0.f;
        const float* acum = g_acum + (size_t)h*SEQ + c*CHUNK;
        float alast = acum[CHUNK-1];
        for (int s0 = 0; s0 < CHUNK; s0 += 32){
            __syncthreads();
            #pragma unroll
            for (int i = 0; i < 8; i++){
                int idx = i*256 + tid; int ssi = idx>>6, n = idx&63;
                int t = c*CHUNK + s0 + ssi;
                sB[idx] = g_xBC[(size_t)t*CONVDIM + DINNER + n];
                float d  = g_dt[(size_t)t*NHEADS + h];
                float dec = __expf(alast - acum[s0+ssi]);
                sX[idx] = g_xBC[(size_t)t*CONVDIM + h*HEADDIM + n] * d * dec;
            }
            __syncthreads();
            for (int ssi = 0; ssi < 32; ssi++){
                float xv = sX[ssi*64 + pi];
                const float4* b4p = (const float4*)(sB + ssi*64 + ng*16);
                #pragma unroll
                for (int j = 0; j < 4; j++){
                    float4 bv = b4p[j];
                    acc[j*4+0] += xv*bv.x; acc[j*4+1] += xv*bv.y;
                    acc[j*4+2] += xv*bv.z; acc[j*4+3] += xv*bv.w;
                }
            }
        }
        float* out = g_S + (size_t)(c*NHEADS + h)*HEADDIM*DSTATE + pi*DSTATE + ng*16;
        #pragma unroll
        for (int j = 0; j < 4; j++)
            *(float4*)(out + j*4) = make_float4(acc[j*4+0], acc[j*4+1], acc[j*4+2], acc[j*4+3]);
    }
}

// ---------------- cross-chunk recurrence (parallel over elements) ----------------
__global__ void k_recur(){
    int idx4 = blockIdx.x*256 + threadIdx.x;      // float4 index, 0..24575
    int h = idx4 >> 10;
    int e = (idx4 & 1023) * 4;
    float4 r = make_float4(0.f, 0.f, 0.f, 0.f);
    #pragma unroll
    for (int c = 0; c < NCHUNK; c++){
        float dec = __expf(g_acum[(size_t)h*SEQ + c*CHUNK + CHUNK-1]);
        size_t base = (size_t)(c*NHEADS + h)*HEADDIM*DSTATE + e;
        *(float4*)(g_prev + base) = r;
        float4 s = *(const float4*)(g_S + base);
        r.x = r.x*dec + s.x; r.y = r.y*dec + s.y;
        r.z = r.z*dec + s.z; r.w = r.w*dec + s.w;
    }
}

// ---------------- fused Y_off + Y_diag ----------------
__global__ __launch_bounds__(256) void k_yoffy(const float* __restrict__ Dskip){
    int c = blockIdx.x, h = blockIdx.y;
    __shared__ __align__(16) float sbuf[4096];
    __shared__ float sac[CHUNK];
    int tid = threadIdx.x, l = tid;
    sac[tid] = g_acum[(size_t)h*SEQ + c*CHUNK + tid];
    size_t base = (size_t)(c*NHEADS + h)*HEADDIM*DSTATE;
    #pragma unroll
    for (int i = 0; i < 16; i++) sbuf[i*256 + tid] = g_prev[base + i*256 + tid];
    __syncthreads();
    float aL = sac[l];
    float eL = __expf(aL);
    float acc[64];
    {
        const float4* Crow = (const float4*)(g_xBC + (size_t)(c*CHUNK + l)*CONVDIM + DINNER + DSTATE);
        float4 cr[16];
        #pragma unroll
        for (int i = 0; i < 16; i++) cr[i] = Crow[i];
        const float4* ps4 = (const float4*)sbuf;
        for (int p = 0; p < HEADDIM; p++){
            float s = 0.f;
            #pragma unroll
            for (int i = 0; i < 16; i++){
                float4 bv = ps4[p*16 + i];
                s += cr[i].x*bv.x + cr[i].y*bv.y + cr[i].z*bv.z + cr[i].w*bv.w;
            }
            acc[p] = eL*s;
        }
    }
    const float* Gt = g_G + (size_t)c*CHUNK*CHUNK;
    float* sX = sbuf;
    for (int s0 = 0; s0 < CHUNK; s0 += 32){
        __syncthreads();
        #pragma unroll
        for (int i = 0; i < 8; i++){
            int idx = i*256 + tid; int ssi = idx>>6, p = idx&63;
            int t = c*CHUNK + s0 + ssi;
            sX[idx] = g_xBC[(size_t)t*CONVDIM + h*HEADDIM + p] * g_dt[(size_t)t*NHEADS + h];
        }
        __syncthreads();
        int smax = l - s0 + 1; if (smax > 32) smax = 32;
        for (int ssi = 0; ssi < smax; ssi++){
            int s = s0 + ssi;
            float g = Gt[(size_t)s*CHUNK + l] * __expf(aL - sac[s]);
            const float4* x4 = (const float4*)(sX + ssi*64);
            #pragma unroll
            for (int p = 0; p < 16; p++){
                float4 xv = x4[p];
                acc[p*4+0] += g*xv.x; acc[p*4+1] += g*xv.y;
                acc[p*4+2] += g*xv.z; acc[p*4+3] += g*xv.w;
            }
        }
    }
    float dsk = Dskip[h];
    int t = c*CHUNK + l;
    float* yo = g_y + (size_t)t*DINNER + h*HEADDIM;
    const float* xr = g_xBC + (size_t)t*CONVDIM + h*HEADDIM;
    #pragma unroll
    for (int p = 0; p < 64; p++) yo[p] = acc[p] + dsk*xr[p];
}

// ---------------- host orchestration ----------------
extern "C" void kernel_launch(void* const* d_in, const int* in_sizes, int n_in,
                              void* d_out, int out_size){
    const int*   ids     = (const int*)  d_in[0];
    const float* emb     = (const float*)d_in[1];
    const float* ln_w    = (const float*)d_in[2];
    const float* in_w    = (const float*)d_in[3];
    const float* conv_w  = (const float*)d_in[4];
    const float* conv_b  = (const float*)d_in[5];
    const float* dt_b    = (const float*)d_in[6];
    const float* A_log   = (const float*)d_in[7];
    const float* D_skip  = (const float*)d_in[8];
    const float* gnorm_w = (const float*)d_in[9];
    const float* out_w   = (const float*)d_in[10];
    const float* norm_f  = (const float*)d_in[11];
    float* out = (float*)d_out;

    float *px, *pzx;
    __nv_bfloat16 *pahi, *palo, *pbhi, *pblo, *pwihi, *pwilo, *pwohi, *pwolo;
    cudaGetSymbolAddress((void**)&px,  g_x);
    cudaGetSymbolAddress((void**)&pzx, g_zx);
    cudaGetSymbolAddress((void**)&pahi, g_ahi);
    cudaGetSymbolAddress((void**)&palo, g_alo);
    cudaGetSymbolAddress((void**)&pbhi, g_bhi);
    cudaGetSymbolAddress((void**)&pblo, g_blo);
    cudaGetSymbolAddress((void**)&pwihi, g_wihi);
    cudaGetSymbolAddress((void**)&pwilo, g_wilo);
    cudaGetSymbolAddress((void**)&pwohi, g_wohi);
    cudaGetSymbolAddress((void**)&pwolo, g_wolo);

    cudaFuncSetAttribute(k_hgemm<0>, cudaFuncAttributeMaxDynamicSharedMemorySize, HG_SMEM);
    cudaFuncSetAttribute(k_hgemm<1>, cudaFuncAttributeMaxDynamicSharedMemorySize, HG_SMEM);

    // ---- prologue: all weight splits (constant data) ----
    k_wsplit_inw<<<(NLAYER*DINPROJ_PAD*DMODEL/8 + 255)/256, 256>>>(in_w, pwihi, pwilo);
    k_wsplit<<<(NLAYER*DMODEL*DINNER/8 + 255)/256, 256>>>(out_w, pwohi, pwolo,
                                                          NLAYER*DMODEL*DINNER, NLAYER*DMODEL*DINNER);
    k_wsplit<<<(VOCAB*DMODEL/8 + 255)/256, 256>>>(emb, pbhi, pblo, VOCAB*DMODEL, VOCAB*DMODEL);

    k_embednorm<<<SEQ, 256>>>(ids, emb, ln_w, pahi, palo);
    for (int i = 0; i < NLAYER; i++){
        k_hgemm<0><<<dim3(DINPROJ_PAD/128, SEQ/128), 256, HG_SMEM>>>(
            pahi, palo,
            pwihi + (size_t)i*DINPROJ_PAD*DMODEL, pwilo + (size_t)i*DINPROJ_PAD*DMODEL,
            pzx, SEQ, DINPROJ, DMODEL);

        k_convcum<<<CONVBLOCKS + NHEADS*NCHUNK, 256>>>(conv_w + (size_t)i*CONVDIM*4,
                                                       conv_b + i*CONVDIM,
                                                       A_log + i*NHEADS, dt_b + i*NHEADS);
        k_Gstates<<<128 + NCHUNK*NHEADS, 256>>>();
        k_recur<<<NHEADS*HEADDIM*DSTATE/4/256, 256>>>();
        k_yoffy<<<dim3(NCHUNK, NHEADS), 256>>>(D_skip + i*NHEADS);
        k_gatenorm_split<<<SEQ, 256>>>(gnorm_w + (size_t)i*DINNER, pahi, palo);

        k_hgemm<1><<<dim3(DMODEL/128, SEQ/128, 2), 256, HG_SMEM>>>(
            pahi, palo,
            pwohi + (size_t)i*DMODEL*DINNER, pwolo + (size_t)i*DMODEL*DINNER,
            pzx, SEQ, DMODEL, DINNER);
        const float* wnext = (i + 1 < NLAYER) ? (ln_w + (size_t)(i+1)*DMODEL) : norm_f;
        k_addnorm<<<SEQ, 256>>>(pzx, pzx + SEQ*DMODEL, wnext, pahi, palo);
    }
    k_hgemm<0><<<dim3(VOCAB/128, SEQ/128), 256, HG_SMEM>>>(
        pahi, palo, pbhi, pblo, out, SEQ, VOCAB, DMODEL);
}